// round 1
// baseline (speedup 1.0000x reference)
#include <cuda_runtime.h>

#define THREADS 128

// All statically-sized scratch lives in dynamic shared memory (~100 KB, 2 blocks/SM).
struct Smem {
  float W[4][64 * 65];   // W1..W4, row j at j*65 (pad-65 => conflict-free column reads); W4 zero-padded to 64 rows
  float B[4][64];        // biases, b4 zero-padded
  float H[2][32 * 65];   // ping-pong activations, 32 nodes (30 real + 2 zero pad) x 64 feats
  float pooled[40];      // 34 used
  float cw1[16 * 5];
  float cb1[16];
  float cw2[32 * 16 * 5];
  float cb2[32];
  float Wo[2 * 352];
  float bo[2];
  float c1[16 * 30];
  float mp[16 * 15];
  float c2[352];
};

__global__ void __launch_bounds__(THREADS, 2) dgcnn_kernel(
    const float* __restrict__ x,
    const float* __restrict__ W1, const float* __restrict__ b1,
    const float* __restrict__ W2, const float* __restrict__ b2,
    const float* __restrict__ W3, const float* __restrict__ b3,
    const float* __restrict__ W4, const float* __restrict__ b4,
    const float* __restrict__ cw1, const float* __restrict__ cb1,
    const float* __restrict__ cw2, const float* __restrict__ cb2,
    const float* __restrict__ Wo, const float* __restrict__ bo,
    float* __restrict__ out, int G, int P)
{
  extern __shared__ char smem_raw[];
  Smem& s = *reinterpret_cast<Smem*>(smem_raw);
  const int tid = threadIdx.x;

  // ---- Stage all weights once per block ----
  for (int idx = tid; idx < 64 * 64; idx += THREADS) {
    int j = idx >> 6, k = idx & 63;
    s.W[0][j * 65 + k] = W1[idx];
    s.W[1][j * 65 + k] = W2[idx];
    s.W[2][j * 65 + k] = W3[idx];
    s.W[3][j * 65 + k] = (j < 34) ? W4[j * 64 + k] : 0.f;
  }
  if (tid < 64) {
    s.B[0][tid] = b1[tid];
    s.B[1][tid] = b2[tid];
    s.B[2][tid] = b3[tid];
    s.B[3][tid] = (tid < 34) ? b4[tid] : 0.f;
  }
  for (int i = tid; i < 80; i += THREADS)   s.cw1[i] = cw1[i];
  if (tid < 16)                             s.cb1[tid] = cb1[tid];
  for (int i = tid; i < 2560; i += THREADS) s.cw2[i] = cw2[i];
  if (tid < 32)                             s.cb2[tid] = cb2[tid];
  for (int i = tid; i < 704; i += THREADS)  s.Wo[i] = Wo[i];
  if (tid < 2)                              s.bo[tid] = bo[tid];
  __syncthreads();

  const int tm = tid & 7;   // node-tile index (8 x 4 nodes = 32)
  const int tn = tid >> 3;  // feat-tile index (16 x 4 feats = 64)

  for (int g = blockIdx.x; g < G; g += gridDim.x) {
    // ---- Load the 30 contributing x rows (pad to 32 with zeros) ----
    const float* xg = x + (long long)g * P * 64;
    for (int idx = tid; idx < 32 * 64; idx += THREADS) {
      int r = idx >> 6, k = idx & 63;
      s.H[0][r * 65 + k] = (r < 30) ? xg[r * 64 + k] : 0.f;
    }
    __syncthreads();

    // ---- 4-layer MLP, register-tiled 4x4 per thread ----
    int cur = 0;
    #pragma unroll
    for (int l = 0; l < 4; l++) {
      const float* Hin  = s.H[cur];
      float*       Hout = s.H[cur ^ 1];
      const float* Wl   = s.W[l];
      float acc[4][4];
      #pragma unroll
      for (int i = 0; i < 4; i++)
        #pragma unroll
        for (int j = 0; j < 4; j++)
          acc[i][j] = s.B[l][tn * 4 + j];

      #pragma unroll 4
      for (int k = 0; k < 64; k++) {
        float a[4], b[4];
        #pragma unroll
        for (int i = 0; i < 4; i++) a[i] = Hin[(tm * 4 + i) * 65 + k];
        #pragma unroll
        for (int j = 0; j < 4; j++) b[j] = Wl[(tn * 4 + j) * 65 + k];
        #pragma unroll
        for (int i = 0; i < 4; i++)
          #pragma unroll
          for (int j = 0; j < 4; j++)
            acc[i][j] = fmaf(a[i], b[j], acc[i][j]);
      }

      #pragma unroll
      for (int i = 0; i < 4; i++)
        #pragma unroll
        for (int j = 0; j < 4; j++)
          Hout[(tm * 4 + i) * 65 + tn * 4 + j] = fmaxf(acc[i][j], 0.f);
      cur ^= 1;
      __syncthreads();
    }
    // after 4 layers cur == 0, h4 lives in s.H[0]

    // ---- Pool: mean over first 30 nodes, feats 0..33 ----
    if (tid < 34) {
      float sum = 0.f;
      #pragma unroll
      for (int r = 0; r < 30; r++) sum += s.H[0][r * 65 + tid];
      s.pooled[tid] = sum * (1.f / 30.f);
    }
    __syncthreads();

    // ---- conv1 (16 out ch, k=5, VALID -> len 30) + ReLU ----
    for (int idx = tid; idx < 16 * 30; idx += THREADS) {
      int c = idx / 30, t = idx % 30;
      float v = s.cb1[c];
      #pragma unroll
      for (int q = 0; q < 5; q++) v = fmaf(s.cw1[c * 5 + q], s.pooled[t + q], v);
      s.c1[c * 30 + t] = fmaxf(v, 0.f);
    }
    __syncthreads();

    // ---- maxpool k=2 s=2 -> len 15 ----
    for (int idx = tid; idx < 16 * 15; idx += THREADS) {
      int c = idx / 15, t = idx % 15;
      s.mp[c * 15 + t] = fmaxf(s.c1[c * 30 + 2 * t], s.c1[c * 30 + 2 * t + 1]);
    }
    __syncthreads();

    // ---- conv2 (32 out ch, 16 in ch, k=5, VALID -> len 11) + ReLU ----
    for (int idx = tid; idx < 32 * 11; idx += THREADS) {
      int c2 = idx / 11, t = idx % 11;
      float v = s.cb2[c2];
      #pragma unroll
      for (int ci = 0; ci < 16; ci++)
        #pragma unroll
        for (int q = 0; q < 5; q++)
          v = fmaf(s.cw2[(c2 * 16 + ci) * 5 + q], s.mp[ci * 15 + t + q], v);
      s.c2[c2 * 11 + t] = fmaxf(v, 0.f);
    }
    __syncthreads();

    // ---- FC: out[g][o] = bo[o] + sum_i Wo[o][i] * flat[i] ----
    if (tid < 64) {
      int o = tid >> 5;
      int lane = tid & 31;
      float sum = 0.f;
      for (int i = lane; i < 352; i += 32) sum = fmaf(s.Wo[o * 352 + i], s.c2[i], sum);
      #pragma unroll
      for (int d = 16; d > 0; d >>= 1) sum += __shfl_down_sync(0xffffffffu, sum, d);
      if (lane == 0) out[g * 2 + o] = sum + s.bo[o];
    }
    __syncthreads();  // protect smem reuse on next group iteration
  }
}

extern "C" void kernel_launch(void* const* d_in, const int* in_sizes, int n_in,
                              void* d_out, int out_size) {
  const float* x   = (const float*)d_in[0];
  // d_in[1] = edge_index (unused by the reference), d_in[2] = batch (structure i//100 is fixed)
  const float* W1  = (const float*)d_in[3];
  const float* b1  = (const float*)d_in[4];
  const float* W2  = (const float*)d_in[5];
  const float* b2  = (const float*)d_in[6];
  const float* W3  = (const float*)d_in[7];
  const float* b3  = (const float*)d_in[8];
  const float* W4  = (const float*)d_in[9];
  const float* b4  = (const float*)d_in[10];
  const float* cw1 = (const float*)d_in[11];
  const float* cb1 = (const float*)d_in[12];
  const float* cw2 = (const float*)d_in[13];
  const float* cb2 = (const float*)d_in[14];
  const float* Wo  = (const float*)d_in[15];
  const float* bo  = (const float*)d_in[16];
  float* out = (float*)d_out;

  int G = out_size / 2;            // 10000
  int N = in_sizes[0] / 64;        // 1000000
  int P = N / G;                   // 100

  int smem = (int)sizeof(Smem);
  cudaFuncSetAttribute(dgcnn_kernel, cudaFuncAttributeMaxDynamicSharedMemorySize, smem);

  dgcnn_kernel<<<304, THREADS, smem>>>(x, W1, b1, W2, b2, W3, b3, W4, b4,
                                       cw1, cb1, cw2, cb2, Wo, bo, out, G, P);
}

// round 2
// speedup vs baseline: 1.1088x; 1.1088x over previous
#include <cuda_runtime.h>
#include <cstdint>

#define THREADS 128
typedef unsigned long long ull;

__device__ __forceinline__ ull pk2(float lo, float hi) {
  ull r; asm("mov.b64 %0, {%1, %2};" : "=l"(r) : "f"(lo), "f"(hi)); return r;
}
__device__ __forceinline__ void unpk2(ull v, float& lo, float& hi) {
  asm("mov.b64 {%0, %1}, %2;" : "=f"(lo), "=f"(hi) : "l"(v));
}
__device__ __forceinline__ ull fma2(ull a, ull b, ull c) {
  ull d; asm("fma.rn.f32x2 %0, %1, %2, %3;" : "=l"(d) : "l"(a), "l"(b), "l"(c)); return d;
}

// Shared layout (~90.6 KB dynamic): weights packed as f32x2 pairs over output
// features (k-major) so the MLP inner loop reads warp-uniform LDS.128 broadcasts.
struct Smem {
  float2 Wp[3][64][32];   // layers 1-3: Wp[l][k][p] = (W[2p][k], W[2p+1][k])
  float2 Wp4[64][18];     // layer 4: 17 real pairs (34 outs) + 1 zero pair (16B-aligned rows)
  float2 Bp[3][32];
  float2 Bp4[18];
  float cw1[80];  float cb1[16];
  float cw2[2560]; float cb2[32];
  float Wo[704];  float bo2[2];
  float pooled[4][40];    // per-warp buffers
  float c1s[4][480];
  float mps[4][240];
  float c2s[4][352];
};

// One MLP layer: h (64 regs in) -> relu(h @ W^T + b) written back into h[0..2*NP).
// Weight reads are warp-uniform (broadcast). NP must be even.
template <int NP>
__device__ __forceinline__ void mlp_layer(const float2* __restrict__ W,
                                          const float2* __restrict__ B,
                                          float* h) {
  ull acc[NP];
#pragma unroll
  for (int p = 0; p < NP; p++) acc[p] = pk2(B[p].x, B[p].y);
#pragma unroll
  for (int k = 0; k < 64; k++) {
    ull hd = pk2(h[k], h[k]);
    const ulonglong2* row = reinterpret_cast<const ulonglong2*>(W + k * NP);
#pragma unroll
    for (int q = 0; q < NP / 2; q++) {
      ulonglong2 w = row[q];
      acc[2 * q]     = fma2(hd, w.x, acc[2 * q]);
      acc[2 * q + 1] = fma2(hd, w.y, acc[2 * q + 1]);
    }
  }
#pragma unroll
  for (int p = 0; p < NP; p++) {
    float a, b; unpk2(acc[p], a, b);
    h[2 * p]     = fmaxf(a, 0.f);
    h[2 * p + 1] = fmaxf(b, 0.f);
  }
}

__global__ void __launch_bounds__(THREADS) dgcnn_kernel(
    const float* __restrict__ x,
    const float* __restrict__ W1, const float* __restrict__ b1,
    const float* __restrict__ W2, const float* __restrict__ b2,
    const float* __restrict__ W3, const float* __restrict__ b3,
    const float* __restrict__ W4, const float* __restrict__ b4,
    const float* __restrict__ cw1, const float* __restrict__ cb1,
    const float* __restrict__ cw2, const float* __restrict__ cb2,
    const float* __restrict__ Wo, const float* __restrict__ bo,
    float* __restrict__ out, int G, int P)
{
  extern __shared__ char smem_raw[];
  Smem& s = *reinterpret_cast<Smem*>(smem_raw);
  const int tid  = threadIdx.x;
  const int w    = tid >> 5;   // warp = group slot (4 per block)
  const int lane = tid & 31;

  // ---- Stage packed weights once per (persistent) block ----
  for (int idx = tid; idx < 3 * 64 * 32; idx += THREADS) {
    int l = idx / 2048, r = idx % 2048, k = r / 32, p = r % 32;
    const float* Wg = (l == 0) ? W1 : (l == 1) ? W2 : W3;
    s.Wp[l][k][p] = make_float2(Wg[(2 * p) * 64 + k], Wg[(2 * p + 1) * 64 + k]);
  }
  for (int idx = tid; idx < 64 * 18; idx += THREADS) {
    int k = idx / 18, p = idx % 18;
    s.Wp4[k][p] = (p < 17)
        ? make_float2(W4[(2 * p) * 64 + k], W4[(2 * p + 1) * 64 + k])
        : make_float2(0.f, 0.f);
  }
  if (tid < 32) {
    s.Bp[0][tid] = make_float2(b1[2 * tid], b1[2 * tid + 1]);
    s.Bp[1][tid] = make_float2(b2[2 * tid], b2[2 * tid + 1]);
    s.Bp[2][tid] = make_float2(b3[2 * tid], b3[2 * tid + 1]);
  }
  if (tid < 18)
    s.Bp4[tid] = (tid < 17) ? make_float2(b4[2 * tid], b4[2 * tid + 1])
                            : make_float2(0.f, 0.f);
  for (int i = tid; i < 80; i += THREADS)   s.cw1[i] = cw1[i];
  if (tid < 16)                             s.cb1[tid] = cb1[tid];
  for (int i = tid; i < 2560; i += THREADS) s.cw2[i] = cw2[i];
  if (tid < 32)                             s.cb2[tid] = cb2[tid];
  for (int i = tid; i < 704; i += THREADS)  s.Wo[i] = Wo[i];
  if (tid < 2)                              s.bo2[tid] = bo[tid];
  __syncthreads();

  const int kc = (P < 30) ? P : 30;     // contributing rows per group
  const float inv = 1.f / (float)kc;
  const int nb = (G + 3) >> 2;          // batches of 4 groups (one per warp)

  for (int b = blockIdx.x; b < nb; b += gridDim.x) {
    const int g = b * 4 + w;
    if (g < G) {
      // ---- Load this lane's node row (registers) ----
      float h[64];
      if (lane < kc) {
        const float4* xr = reinterpret_cast<const float4*>(x + ((size_t)g * P + lane) * 64);
#pragma unroll
        for (int q = 0; q < 16; q++) {
          float4 v = xr[q];
          h[4 * q] = v.x; h[4 * q + 1] = v.y; h[4 * q + 2] = v.z; h[4 * q + 3] = v.w;
        }
      } else {
#pragma unroll
        for (int k = 0; k < 64; k++) h[k] = 0.f;
      }

      // ---- 4-layer MLP entirely in registers ----
      mlp_layer<32>(&s.Wp[0][0][0], s.Bp[0], h);
      mlp_layer<32>(&s.Wp[1][0][0], s.Bp[1], h);
      mlp_layer<32>(&s.Wp[2][0][0], s.Bp[2], h);
      mlp_layer<18>(&s.Wp4[0][0],   s.Bp4,   h);   // 34 real outputs in h[0..33]

      // ---- Pool: mean over the kc contributing lanes (warp butterfly) ----
      float v[34];
#pragma unroll
      for (int f = 0; f < 34; f++) v[f] = (lane < kc) ? h[f] : 0.f;
#pragma unroll
      for (int f = 0; f < 34; f++) {
#pragma unroll
        for (int d = 16; d > 0; d >>= 1) v[f] += __shfl_xor_sync(0xffffffffu, v[f], d);
      }
      if (lane == 0) {
#pragma unroll
        for (int f = 0; f < 34; f++) s.pooled[w][f] = v[f] * inv;
      }
      __syncwarp();

      // ---- conv1 (16ch, k=5 -> len 30) + ReLU ----
      for (int idx = lane; idx < 480; idx += 32) {
        int c = idx / 30, t = idx % 30;
        float a = s.cb1[c];
#pragma unroll
        for (int q = 0; q < 5; q++) a = fmaf(s.cw1[c * 5 + q], s.pooled[w][t + q], a);
        s.c1s[w][c * 30 + t] = fmaxf(a, 0.f);
      }
      __syncwarp();

      // ---- maxpool k=2 s=2 -> len 15 ----
      for (int idx = lane; idx < 240; idx += 32) {
        int c = idx / 15, t = idx % 15;
        s.mps[w][c * 15 + t] = fmaxf(s.c1s[w][c * 30 + 2 * t], s.c1s[w][c * 30 + 2 * t + 1]);
      }
      __syncwarp();

      // ---- conv2 (32ch, 16 in, k=5 -> len 11) + ReLU ----
      for (int idx = lane; idx < 352; idx += 32) {
        int c2 = idx / 11, t = idx % 11;
        float a = s.cb2[c2];
#pragma unroll
        for (int ci = 0; ci < 16; ci++)
#pragma unroll
          for (int q = 0; q < 5; q++)
            a = fmaf(s.cw2[(c2 * 16 + ci) * 5 + q], s.mps[w][ci * 15 + t + q], a);
        s.c2s[w][c2 * 11 + t] = fmaxf(a, 0.f);
      }
      __syncwarp();

      // ---- FC 352 -> 2 (warp reduce) ----
      float s0 = 0.f, s1 = 0.f;
      for (int i = lane; i < 352; i += 32) {
        float c = s.c2s[w][i];
        s0 = fmaf(s.Wo[i], c, s0);
        s1 = fmaf(s.Wo[352 + i], c, s1);
      }
#pragma unroll
      for (int d = 16; d > 0; d >>= 1) {
        s0 += __shfl_xor_sync(0xffffffffu, s0, d);
        s1 += __shfl_xor_sync(0xffffffffu, s1, d);
      }
      if (lane == 0) {
        out[g * 2 + 0] = s0 + s.bo2[0];
        out[g * 2 + 1] = s1 + s.bo2[1];
      }
      __syncwarp();
    }
  }
}

extern "C" void kernel_launch(void* const* d_in, const int* in_sizes, int n_in,
                              void* d_out, int out_size) {
  const float* x   = (const float*)d_in[0];
  // d_in[1] = edge_index (unused by reference), d_in[2] = batch (i // (N/G))
  const float* W1  = (const float*)d_in[3];
  const float* b1  = (const float*)d_in[4];
  const float* W2  = (const float*)d_in[5];
  const float* b2  = (const float*)d_in[6];
  const float* W3  = (const float*)d_in[7];
  const float* b3  = (const float*)d_in[8];
  const float* W4  = (const float*)d_in[9];
  const float* b4  = (const float*)d_in[10];
  const float* cw1 = (const float*)d_in[11];
  const float* cb1 = (const float*)d_in[12];
  const float* cw2 = (const float*)d_in[13];
  const float* cb2 = (const float*)d_in[14];
  const float* Wo  = (const float*)d_in[15];
  const float* bo  = (const float*)d_in[16];
  float* out = (float*)d_out;

  int G = out_size / 2;       // 10000
  int N = in_sizes[0] / 64;   // 1000000
  int P = N / G;              // 100

  int smem = (int)sizeof(Smem);
  cudaFuncSetAttribute(dgcnn_kernel, cudaFuncAttributeMaxDynamicSharedMemorySize, smem);

  dgcnn_kernel<<<304, THREADS, smem>>>(x, W1, b1, W2, b2, W3, b3, W4, b4,
                                       cw1, cb1, cw2, cb2, Wo, bo, out, G, P);
}

// round 4
// speedup vs baseline: 3.0992x; 2.7950x over previous
#include <cuda_runtime.h>
#include <cstdint>

#define THREADS 256
#define NW 8            // warps per block
#define GRID 152

typedef unsigned long long ull;

__device__ __forceinline__ ull pk2(float lo, float hi) {
  ull r; asm("mov.b64 %0, {%1, %2};" : "=l"(r) : "f"(lo), "f"(hi)); return r;
}
__device__ __forceinline__ void unpk2(ull v, float& lo, float& hi) {
  asm("mov.b64 {%0, %1}, %2;" : "=f"(lo), "=f"(hi) : "l"(v));
}
__device__ __forceinline__ ull fma2(ull a, ull b, ull c) {
  ull d; asm("fma.rn.f32x2 %0, %1, %2, %3;" : "=l"(d) : "l"(a), "l"(b), "l"(c)); return d;
}

// ~156 KB dynamic shared memory, 1 block (8 warps) per SM.
// alignas(16) on every member touched via float4 / ulonglong2 — R3 faulted
// because H landed at struct offset ≡ 8 (mod 16).
struct Smem {
  alignas(16) float2 Wp[3][64][32];    // layers 1-3: Wp[l][k][P] = (W[2P][k], W[2P+1][k])
  alignas(16) float2 Wp4[64][20];      // layer 4: pairs 0..16 real (34 outs), 17..19 zero
  alignas(16) float2 Bp[3][32];
  alignas(16) float2 Bp4[20];
  float  cw1t[5][16];      // [q][c]   (lane-distinct reads)
  float  cb1[16];
  float  cw2t[16][5][32];  // [ci][q][c2]
  float  cb2[32];
  float  Wo[704];
  float  bo2[2];
  alignas(16) float  H[NW][64 * 32];   // per-warp activation tile, k-major, bank-swizzled
  alignas(16) float  pooled[NW][40];
  alignas(16) float  mps[NW][16][16];  // mp rows padded 15->16 (float4-aligned)
  alignas(16) float  c2s[NW][352];
};

// swizzled float-index of H element (row k / feature f, float column c 0..31):
// column group (c>>2) rotated by (k>>4) so the writeback's 4 concurrent rows
// (16 apart) land in distinct bank groups.
__device__ __forceinline__ int hidx(int k, int c) {
  return k * 32 + ((((c >> 2) + (k >> 4)) & 7) << 2) + (c & 3);
}

// Layers 1-3: warp covers 32 nodes x 64 outputs; lane tile = 4 nodes x 8 pairs.
__device__ __forceinline__ void mlp8x4(const float2* __restrict__ Wk,  // [64][32]
                                       const float2* __restrict__ Bp,  // [32]
                                       float* __restrict__ Hw,         // [64*32]
                                       int nl, int ol) {
  ull acc[4][8];
#pragma unroll
  for (int p = 0; p < 8; p++) {
    float2 b = Bp[8 * ol + p];
    ull bb = pk2(b.x, b.y);
#pragma unroll
    for (int n = 0; n < 4; n++) acc[n][p] = bb;
  }
#pragma unroll 8
  for (int k = 0; k < 64; k++) {
    const float4 hv = *reinterpret_cast<const float4*>(Hw + hidx(k, 4 * nl));
    ull hd0 = pk2(hv.x, hv.x), hd1 = pk2(hv.y, hv.y);
    ull hd2 = pk2(hv.z, hv.z), hd3 = pk2(hv.w, hv.w);
    const ulonglong2* wr = reinterpret_cast<const ulonglong2*>(Wk + k * 32 + 8 * ol);
#pragma unroll
    for (int qq = 0; qq < 4; qq++) {
      ulonglong2 wp = wr[qq];
      acc[0][2*qq]   = fma2(hd0, wp.x, acc[0][2*qq]);
      acc[1][2*qq]   = fma2(hd1, wp.x, acc[1][2*qq]);
      acc[2][2*qq]   = fma2(hd2, wp.x, acc[2][2*qq]);
      acc[3][2*qq]   = fma2(hd3, wp.x, acc[3][2*qq]);
      acc[0][2*qq+1] = fma2(hd0, wp.y, acc[0][2*qq+1]);
      acc[1][2*qq+1] = fma2(hd1, wp.y, acc[1][2*qq+1]);
      acc[2][2*qq+1] = fma2(hd2, wp.y, acc[2][2*qq+1]);
      acc[3][2*qq+1] = fma2(hd3, wp.y, acc[3][2*qq+1]);
    }
  }
  // relu + in-place writeback (all reads above precede writes in warp program order)
#pragma unroll
  for (int p = 0; p < 8; p++) {
    int P = 8 * ol + p;
    float e[4], o[4];
#pragma unroll
    for (int n = 0; n < 4; n++) {
      unpk2(acc[n][p], e[n], o[n]);
      e[n] = fmaxf(e[n], 0.f); o[n] = fmaxf(o[n], 0.f);
    }
    int fe = 2 * P, fo = 2 * P + 1;
    *reinterpret_cast<float4*>(Hw + hidx(fe, 4 * nl)) = make_float4(e[0], e[1], e[2], e[3]);
    *reinterpret_cast<float4*>(Hw + hidx(fo, 4 * nl)) = make_float4(o[0], o[1], o[2], o[3]);
  }
}

__global__ void __launch_bounds__(THREADS, 1) dgcnn_kernel(
    const float* __restrict__ x,
    const float* __restrict__ W1, const float* __restrict__ b1,
    const float* __restrict__ W2, const float* __restrict__ b2,
    const float* __restrict__ W3, const float* __restrict__ b3,
    const float* __restrict__ W4, const float* __restrict__ b4,
    const float* __restrict__ cw1, const float* __restrict__ cb1,
    const float* __restrict__ cw2, const float* __restrict__ cb2,
    const float* __restrict__ Wo, const float* __restrict__ bo,
    float* __restrict__ out, int G, int P)
{
  extern __shared__ __align__(16) char smem_raw[];
  Smem& s = *reinterpret_cast<Smem*>(smem_raw);
  const int tid  = threadIdx.x;
  const int w    = tid >> 5;
  const int lane = tid & 31;

  // ---- Stage packed weights once per block ----
  for (int idx = tid; idx < 3 * 64 * 32; idx += THREADS) {
    int l = idx >> 11, rem = idx & 2047, k = rem >> 5, p = rem & 31;
    const float* Wg = (l == 0) ? W1 : (l == 1) ? W2 : W3;
    s.Wp[l][k][p] = make_float2(Wg[(2 * p) * 64 + k], Wg[(2 * p + 1) * 64 + k]);
  }
  for (int idx = tid; idx < 64 * 20; idx += THREADS) {
    int k = idx / 20, p = idx % 20;
    s.Wp4[k][p] = (p < 17)
        ? make_float2(W4[(2 * p) * 64 + k], W4[(2 * p + 1) * 64 + k])
        : make_float2(0.f, 0.f);
  }
  if (tid < 32) {
    s.Bp[0][tid] = make_float2(b1[2 * tid], b1[2 * tid + 1]);
    s.Bp[1][tid] = make_float2(b2[2 * tid], b2[2 * tid + 1]);
    s.Bp[2][tid] = make_float2(b3[2 * tid], b3[2 * tid + 1]);
  }
  if (tid < 20)
    s.Bp4[tid] = (tid < 17) ? make_float2(b4[2 * tid], b4[2 * tid + 1])
                            : make_float2(0.f, 0.f);
  for (int i = tid; i < 80; i += THREADS) { int q = i >> 4, c = i & 15; s.cw1t[q][c] = cw1[c * 5 + q]; }
  if (tid < 16)  s.cb1[tid] = cb1[tid];
  for (int i = tid; i < 2560; i += THREADS) {
    int ci = i / 160, r = i % 160, q = r >> 5, c2 = r & 31;
    s.cw2t[ci][q][c2] = cw2[(c2 * 16 + ci) * 5 + q];
  }
  if (tid < 32)  s.cb2[tid] = cb2[tid];
  for (int i = tid; i < 704; i += THREADS) s.Wo[i] = Wo[i];
  if (tid < 2)   s.bo2[tid] = bo[tid];
  __syncthreads();

  const int kc = (P < 30) ? P : 30;
  const float inv = 1.f / (float)kc;
  float* Hw = s.H[w];
  const int nl8 = lane & 7,  ol8 = lane >> 3;   // layers 1-3 mapping
  const int nl4 = lane & 15, ol4 = lane >> 4;   // layer-4 mapping

  for (int g = blockIdx.x * NW + w; g < G; g += GRID * NW) {
    // ---- Load x rows into H (k-major, swizzled); pad nodes -> 0 ----
    {
      int src = (lane < kc) ? lane : 0;
      const float4* xr = reinterpret_cast<const float4*>(x + ((size_t)g * P + src) * 64);
      bool act = lane < kc;
#pragma unroll
      for (int q = 0; q < 16; q++) {
        float4 v = act ? xr[q] : make_float4(0.f, 0.f, 0.f, 0.f);
        int k0 = 4 * q;
        Hw[hidx(k0 + 0, lane)] = v.x;
        Hw[hidx(k0 + 1, lane)] = v.y;
        Hw[hidx(k0 + 2, lane)] = v.z;
        Hw[hidx(k0 + 3, lane)] = v.w;
      }
    }
    __syncwarp();

    // ---- Layers 1-3 ----
    mlp8x4(&s.Wp[0][0][0], s.Bp[0], Hw, nl8, ol8);
    mlp8x4(&s.Wp[1][0][0], s.Bp[1], Hw, nl8, ol8);
    mlp8x4(&s.Wp[2][0][0], s.Bp[2], Hw, nl8, ol8);

    // ---- Layer 4 (2 nodes x 10 pairs per lane) + pooling from accumulators ----
    {
      ull acc[2][10];
#pragma unroll
      for (int p = 0; p < 10; p++) {
        float2 b = s.Bp4[10 * ol4 + p];
        ull bb = pk2(b.x, b.y);
        acc[0][p] = bb; acc[1][p] = bb;
      }
#pragma unroll 8
      for (int k = 0; k < 64; k++) {
        const float2 hv = *reinterpret_cast<const float2*>(
            Hw + k * 32 + ((((nl4 >> 1) + (k >> 4)) & 7) << 2) + 2 * (nl4 & 1));
        ull h0 = pk2(hv.x, hv.x), h1 = pk2(hv.y, hv.y);
        const ulonglong2* wr = reinterpret_cast<const ulonglong2*>(&s.Wp4[k][10 * ol4]);
#pragma unroll
        for (int qq = 0; qq < 5; qq++) {
          ulonglong2 wp = wr[qq];
          acc[0][2*qq]   = fma2(h0, wp.x, acc[0][2*qq]);
          acc[1][2*qq]   = fma2(h1, wp.x, acc[1][2*qq]);
          acc[0][2*qq+1] = fma2(h0, wp.y, acc[0][2*qq+1]);
          acc[1][2*qq+1] = fma2(h1, wp.y, acc[1][2*qq+1]);
        }
      }
      // relu + node mask + mean-pool via half-warp butterfly
      float m0 = (2 * nl4     < kc) ? 1.f : 0.f;
      float m1 = (2 * nl4 + 1 < kc) ? 1.f : 0.f;
      float se[10], so[10];
#pragma unroll
      for (int p = 0; p < 10; p++) {
        float a0e, a0o, a1e, a1o;
        unpk2(acc[0][p], a0e, a0o);
        unpk2(acc[1][p], a1e, a1o);
        se[p] = m0 * fmaxf(a0e, 0.f) + m1 * fmaxf(a1e, 0.f);
        so[p] = m0 * fmaxf(a0o, 0.f) + m1 * fmaxf(a1o, 0.f);
      }
#pragma unroll
      for (int d = 1; d < 16; d <<= 1) {
#pragma unroll
        for (int p = 0; p < 10; p++) {
          se[p] += __shfl_xor_sync(0xffffffffu, se[p], d);
          so[p] += __shfl_xor_sync(0xffffffffu, so[p], d);
        }
      }
      if (nl4 == 0) {
#pragma unroll
        for (int p = 0; p < 10; p++) {
          int f = 20 * ol4 + 2 * p;
          if (f < 34) {
            s.pooled[w][f]     = se[p] * inv;
            s.pooled[w][f + 1] = so[p] * inv;
          }
        }
      }
    }
    __syncwarp();

    // ---- conv1 (16ch,k=5 -> 30) + ReLU + maxpool2 -> mps[16][15] ----
    {
      int c = lane & 15, h = lane >> 4;   // lane computes c1[c][t], t = 2s+h
      float wq[5];
#pragma unroll
      for (int q = 0; q < 5; q++) wq[q] = s.cw1t[q][c];
      float bc = s.cb1[c];
#pragma unroll
      for (int sIdx = 0; sIdx < 15; sIdx++) {
        int t = 2 * sIdx + h;
        float a = bc;
#pragma unroll
        for (int q = 0; q < 5; q++) a = fmaf(wq[q], s.pooled[w][t + q], a);
        a = fmaxf(a, 0.f);
        float mv = fmaxf(a, __shfl_xor_sync(0xffffffffu, a, 16));
        if (h == 0) s.mps[w][c][sIdx] = mv;
      }
    }
    __syncwarp();

    // ---- conv2 (32ch,16in,k=5 -> 11) + ReLU ----
    {
      int c2 = lane;
      float a11[11];
#pragma unroll
      for (int t = 0; t < 11; t++) a11[t] = s.cb2[c2];
#pragma unroll
      for (int ci = 0; ci < 16; ci++) {
        const float4* mr = reinterpret_cast<const float4*>(&s.mps[w][ci][0]);
        float4 A = mr[0], B = mr[1], C = mr[2], D = mr[3];
        float m[16] = {A.x,A.y,A.z,A.w, B.x,B.y,B.z,B.w, C.x,C.y,C.z,C.w, D.x,D.y,D.z,D.w};
#pragma unroll
        for (int q = 0; q < 5; q++) {
          float wv = s.cw2t[ci][q][c2];
#pragma unroll
          for (int t = 0; t < 11; t++) a11[t] = fmaf(wv, m[t + q], a11[t]);
        }
      }
#pragma unroll
      for (int t = 0; t < 11; t++) s.c2s[w][c2 * 11 + t] = fmaxf(a11[t], 0.f);
    }
    __syncwarp();

    // ---- FC 352 -> 2 ----
    {
      float s0 = 0.f, s1 = 0.f;
#pragma unroll
      for (int j = 0; j < 11; j++) {
        int i = lane + 32 * j;
        float c = s.c2s[w][i];
        s0 = fmaf(s.Wo[i], c, s0);
        s1 = fmaf(s.Wo[352 + i], c, s1);
      }
#pragma unroll
      for (int d = 16; d > 0; d >>= 1) {
        s0 += __shfl_xor_sync(0xffffffffu, s0, d);
        s1 += __shfl_xor_sync(0xffffffffu, s1, d);
      }
      if (lane == 0) {
        out[g * 2 + 0] = s0 + s.bo2[0];
        out[g * 2 + 1] = s1 + s.bo2[1];
      }
    }
    __syncwarp();
  }
}

extern "C" void kernel_launch(void* const* d_in, const int* in_sizes, int n_in,
                              void* d_out, int out_size) {
  const float* x   = (const float*)d_in[0];
  // d_in[1] = edge_index (unused by reference), d_in[2] = batch (i // (N/G))
  const float* W1  = (const float*)d_in[3];
  const float* b1  = (const float*)d_in[4];
  const float* W2  = (const float*)d_in[5];
  const float* b2  = (const float*)d_in[6];
  const float* W3  = (const float*)d_in[7];
  const float* b3  = (const float*)d_in[8];
  const float* W4  = (const float*)d_in[9];
  const float* b4  = (const float*)d_in[10];
  const float* cw1 = (const float*)d_in[11];
  const float* cb1 = (const float*)d_in[12];
  const float* cw2 = (const float*)d_in[13];
  const float* cb2 = (const float*)d_in[14];
  const float* Wo  = (const float*)d_in[15];
  const float* bo  = (const float*)d_in[16];
  float* out = (float*)d_out;

  int G = out_size / 2;       // 10000
  int N = in_sizes[0] / 64;   // 1000000
  int P = N / G;              // 100

  int smem = (int)sizeof(Smem);
  cudaFuncSetAttribute(dgcnn_kernel, cudaFuncAttributeMaxDynamicSharedMemorySize, smem);

  dgcnn_kernel<<<GRID, THREADS, smem>>>(x, W1, b1, W2, b2, W3, b3, W4, b4,
                                        cw1, cb1, cw2, cb2, Wo, bo, out, G, P);
}